// round 7
// baseline (speedup 1.0000x reference)
#include <cuda_runtime.h>
#include <cuda_bf16.h>
#include <cstdint>
#include <cstddef>

// Problem constants
#define BB    4
#define NN    4096
#define DIN   256
#define DOUT  128
#define COS_EPS    0.001f
#define THRESHOLD  0.1f
#define LEAKY      0.01f
#define FIX_WIN    2e-4f
#define MAXFIX     (1u << 22)

// ---------------------------------------------------------------------------
// Scratch (static device globals; no allocations allowed)
// ---------------------------------------------------------------------------
__device__ float          g_h[BB * NN * DOUT];     // fp32 h (fixup)
__device__ signed char    g_qa[BB * NN * DOUT];    // int8 a-plane
__device__ signed char    g_qb[BB * NN * DOUT];    // int8 b-plane (residual*128)
__device__ float          g_norm[BB * NN];
__device__ float          g_scale[BB * NN];        // s = rowmax/127
__device__ float          g_srn[BB * NN];          // s * (1/norm)
__device__ unsigned int   g_fix_cnt;
__device__ unsigned int   g_fix[MAXFIX];

__device__ __forceinline__ uint32_t smem_u32(const void* p) {
    uint32_t a;
    asm("{ .reg .u64 t; cvta.to.shared.u64 t, %1; cvt.u32.u64 %0, t; }"
        : "=r"(a) : "l"(p));
    return a;
}

__device__ __forceinline__ void ldsm_x4(uint32_t* r, uint32_t addr) {
    asm volatile("ldmatrix.sync.aligned.m8n8.x4.shared.b16 {%0,%1,%2,%3}, [%4];"
                 : "=r"(r[0]), "=r"(r[1]), "=r"(r[2]), "=r"(r[3]) : "r"(addr));
}
__device__ __forceinline__ void mma_s8(int* d, const uint32_t* a, const uint32_t* b) {
    asm volatile(
        "mma.sync.aligned.m16n8k32.row.col.s32.s8.s8.s32 "
        "{%0,%1,%2,%3}, {%4,%5,%6,%7}, {%8,%9}, {%0,%1,%2,%3};"
        : "+r"(d[0]), "+r"(d[1]), "+r"(d[2]), "+r"(d[3])
        : "r"(a[0]), "r"(a[1]), "r"(a[2]), "r"(a[3]), "r"(b[0]), "r"(b[1]));
}

extern __shared__ char smem_raw[];

// ---------------------------------------------------------------------------
// Kernel A: h = leaky_relu(z @ W)  +  fused per-row norm & int8 2-plane quant
// ---------------------------------------------------------------------------
#define Z_ROWLEN 132
__global__ void __launch_bounds__(256, 1)
gemm1_kernel(const float* __restrict__ z, const float* __restrict__ W)
{
    float* smem = (float*)smem_raw;
    float* Zs = smem;
    float* Ws = smem + 64 * Z_ROWLEN;

    const int m0  = blockIdx.x * 128;
    const int tid = threadIdx.x;
    const int tm  = tid >> 4;
    const int tn  = tid & 15;

    float acc[8][8];
#pragma unroll
    for (int i = 0; i < 8; i++)
#pragma unroll
        for (int j = 0; j < 8; j++) acc[i][j] = 0.f;

    for (int k0 = 0; k0 < DIN; k0 += 64) {
#pragma unroll
        for (int t = 0; t < 8; t++) {
            int idx = tid + t * 256;
            int r   = idx >> 4;
            int kk  = (idx & 15) << 2;
            float4 v = *(const float4*)(z + (size_t)(m0 + r) * DIN + k0 + kk);
            Zs[(kk + 0) * Z_ROWLEN + r] = v.x;
            Zs[(kk + 1) * Z_ROWLEN + r] = v.y;
            Zs[(kk + 2) * Z_ROWLEN + r] = v.z;
            Zs[(kk + 3) * Z_ROWLEN + r] = v.w;
        }
#pragma unroll
        for (int t = 0; t < 8; t++) {
            int idx = tid + t * 256;
            int kk  = idx >> 5;
            int n4  = (idx & 31) << 2;
            float4 v = *(const float4*)(W + (size_t)(k0 + kk) * DOUT + n4);
            *(float4*)&Ws[kk * DOUT + n4] = v;
        }
        __syncthreads();

#pragma unroll 8
        for (int k = 0; k < 64; k++) {
            float a[8], b[8];
            *(float4*)(a)     = *(float4*)&Zs[k * Z_ROWLEN + tm * 8];
            *(float4*)(a + 4) = *(float4*)&Zs[k * Z_ROWLEN + tm * 8 + 4];
            *(float4*)(b)     = *(float4*)&Ws[k * DOUT + tn * 8];
            *(float4*)(b + 4) = *(float4*)&Ws[k * DOUT + tn * 8 + 4];
#pragma unroll
            for (int i = 0; i < 8; i++)
#pragma unroll
                for (int j = 0; j < 8; j++)
                    acc[i][j] += a[i] * b[j];
        }
        __syncthreads();
    }

    // Epilogue: leaky relu, row norm + rowmax (16-lane reductions), quantize
#pragma unroll
    for (int i = 0; i < 8; i++) {
        int row = m0 + tm * 8 + i;
        float vv[8];
        float ss = 0.f, mm = 0.f;
#pragma unroll
        for (int j = 0; j < 8; j++) {
            float x = acc[i][j];
            float v = (x > 0.f) ? x : LEAKY * x;
            vv[j] = v;
            ss += v * v;
            mm = fmaxf(mm, fabsf(v));
        }
#pragma unroll
        for (int off = 1; off < 16; off <<= 1) {
            ss += __shfl_xor_sync(0xFFFFFFFFu, ss, off);
            mm = fmaxf(mm, __shfl_xor_sync(0xFFFFFFFFu, mm, off));
        }

        // fp32 h for fixup
        float* dst = g_h + (size_t)row * DOUT + tn * 8;
        *(float4*)(dst)     = make_float4(vv[0], vv[1], vv[2], vv[3]);
        *(float4*)(dst + 4) = make_float4(vv[4], vv[5], vv[6], vv[7]);

        float s   = mm * (1.0f / 127.0f);
        float inv = (mm > 0.f) ? (127.0f / mm) : 0.f;

        union { signed char c[8]; uint2 u; } pa, pb;
#pragma unroll
        for (int j = 0; j < 8; j++) {
            float t  = vv[j] * inv;
            int   ai = __float2int_rn(t);
            int   bi = __float2int_rn(128.0f * (t - (float)ai));
            pa.c[j] = (signed char)ai;
            pb.c[j] = (signed char)bi;
        }
        *(uint2*)(g_qa + (size_t)row * DOUT + tn * 8) = pa.u;
        *(uint2*)(g_qb + (size_t)row * DOUT + tn * 8) = pb.u;

        if (tn == 0) {
            float n  = sqrtf(ss);
            float rn = (n > 0.f) ? (1.0f / n) : 0.f;
            g_norm[row]  = n;
            g_scale[row] = s;
            g_srn[row]   = s * rn;
        }
    }
}

__global__ void reset_kernel() { g_fix_cnt = 0; }

// ---------------------------------------------------------------------------
// Kernel C: int8 IMMA Gram (3 passes: AA, AB, BA; BB dropped ~1e-5 of v).
// 512 threads, 16 warps (4m x 4n), warp tile 32x32, K=128 (4 ksteps of 32).
// Smem int8 tiles: [128 rows][128 B], 16B chunks XOR-swizzled by (row&7).
// Triangular grid: blockIdx.x in [0,528) -> (bx,by), by >= bx.
// ---------------------------------------------------------------------------
#define QOFF_A_A    0
#define QOFF_A_B    16384
#define QOFF_B_A    32768
#define QOFF_B_B    49152
#define OFF_PARAMS  66048                 /* after stage (128*129*4=66048) */
#define OFF_NA      (OFF_PARAMS)
#define OFF_NB      (OFF_PARAMS + 512)
#define OFF_FA      (OFF_PARAMS + 1024)
#define OFF_FB      (OFF_PARAMS + 1536)
#define OFF_SA      (OFF_PARAMS + 2048)
#define OFF_SB      (OFF_PARAMS + 2560)
#define GRAM_SMEM   (OFF_PARAMS + 3072)
#define OFF_STAGE   0
#define STAGE_LD    129

__global__ void __launch_bounds__(512, 1)
gram_imma_kernel(float* __restrict__ out)
{
    // Triangular tile index -> (bx, by) with by >= bx
    int tt = blockIdx.x;
    int by = (int)((sqrtf(8.f * tt + 1.f) - 1.f) * 0.5f);
    while ((by + 1) * (by + 2) / 2 <= tt) by++;
    while (by * (by + 1) / 2 > tt) by--;
    const int bx = tt - by * (by + 1) / 2;
    const int b  = blockIdx.y;

    char* smem = smem_raw;
    const uint32_t sb = smem_u32(smem);
    const int tid  = threadIdx.x;
    const int lane = tid & 31;
    const int wid  = tid >> 5;
    const int warp_m = wid >> 2;
    const int warp_n = wid & 3;

    const int i0 = bx * 128, j0 = by * 128;
    const size_t qbase = (size_t)b * NN * DOUT;
    const size_t nbase = (size_t)b * NN;

    // ---- Load 4 int8 operand tiles (16KB each), swizzled ----
    {
        const uint4* sAa = (const uint4*)(g_qa + qbase + (size_t)i0 * DOUT);
        const uint4* sAb = (const uint4*)(g_qb + qbase + (size_t)i0 * DOUT);
        const uint4* sBa = (const uint4*)(g_qa + qbase + (size_t)j0 * DOUT);
        const uint4* sBb = (const uint4*)(g_qb + qbase + (size_t)j0 * DOUT);
#pragma unroll
        for (int t = 0; t < 2; t++) {
            int idx = tid + t * 512;            // 0..1023 uint4 per region
            int row = idx >> 3;                 // 8 chunks per 128B row
            int c   = idx & 7;
            uint32_t off = (uint32_t)(row * 128) + (uint32_t)((c ^ (row & 7)) << 4);
            *(uint4*)(smem + QOFF_A_A + off) = sAa[idx];
            *(uint4*)(smem + QOFF_A_B + off) = sAb[idx];
            *(uint4*)(smem + QOFF_B_A + off) = sBa[idx];
            *(uint4*)(smem + QOFF_B_B + off) = sBb[idx];
        }
        if (tid < 128) {
            ((float*)(smem + OFF_NA))[tid] = g_norm[nbase + i0 + tid];
            ((float*)(smem + OFF_NB))[tid] = g_norm[nbase + j0 + tid];
            ((float*)(smem + OFF_FA))[tid] = g_srn[nbase + i0 + tid];
            ((float*)(smem + OFF_FB))[tid] = g_srn[nbase + j0 + tid];
            ((float*)(smem + OFF_SA))[tid] = g_scale[nbase + i0 + tid];
            ((float*)(smem + OFF_SB))[tid] = g_scale[nbase + j0 + tid];
        }
    }
    __syncthreads();

    // ---- IMMA mainloop: 12 steps = 3 passes (AA, AB, BA) x 4 ksteps ----
    int accAA[2][4][4], accX[2][4][4];
#pragma unroll
    for (int mf = 0; mf < 2; mf++)
#pragma unroll
        for (int ng = 0; ng < 4; ng++)
#pragma unroll
            for (int r = 0; r < 4; r++) { accAA[mf][ng][r] = 0; accX[mf][ng][r] = 0; }

    const uint32_t aoffs[3] = { sb + QOFF_A_A, sb + QOFF_A_A, sb + QOFF_A_B };
    const uint32_t boffs[3] = { sb + QOFF_B_A, sb + QOFF_B_B, sb + QOFF_B_A };

    // A ldsm lanes: g0 rows0-7 chunk lo, g1 rows8-15 chunk lo, g2 rows0-7 hi, g3 rows8-15 hi
    const int a_row  = warp_m * 32 + (((lane >> 3) & 1) << 3) + (lane & 7);
    const int a_sel  = lane >> 4;
    const int a_swz  = a_row & 7;                 // +16 keeps low 3 bits
    const uint32_t a_rb0 = (uint32_t)(a_row * 128);
    const uint32_t a_rb1 = (uint32_t)((a_row + 16) * 128);
    // B ldsm lanes: g0 rows0-7 chunk lo, g1 rows0-7 hi, g2 rows8-15 lo, g3 rows8-15 hi
    const int b_row  = warp_n * 32 + ((lane >> 4) << 3) + (lane & 7);
    const int b_sel  = (lane >> 3) & 1;
    const int b_swz  = b_row & 7;
    const uint32_t b_rb0 = (uint32_t)(b_row * 128);
    const uint32_t b_rb1 = (uint32_t)((b_row + 16) * 128);

    uint32_t abuf[2][2][4], bbuf[2][2][4];

    // prefetch step 0 (pass 0, kstep 0)
    {
        uint32_t ac = (uint32_t)((0 + a_sel) ^ a_swz) << 4;
        uint32_t bc = (uint32_t)((0 + b_sel) ^ b_swz) << 4;
        ldsm_x4(abuf[0][0], aoffs[0] + a_rb0 + ac);
        ldsm_x4(abuf[0][1], aoffs[0] + a_rb1 + ac);
        ldsm_x4(bbuf[0][0], boffs[0] + b_rb0 + bc);
        ldsm_x4(bbuf[0][1], boffs[0] + b_rb1 + bc);
    }

#pragma unroll
    for (int s = 0; s < 12; s++) {
        const int cur = s & 1;
        if (s < 11) {
            const int sn = s + 1;
            const int pn = sn >> 2, kn = sn & 3;
            const int nxt = sn & 1;
            uint32_t ac = (uint32_t)((kn * 2 + a_sel) ^ a_swz) << 4;
            uint32_t bc = (uint32_t)((kn * 2 + b_sel) ^ b_swz) << 4;
            ldsm_x4(abuf[nxt][0], aoffs[pn] + a_rb0 + ac);
            ldsm_x4(abuf[nxt][1], aoffs[pn] + a_rb1 + ac);
            ldsm_x4(bbuf[nxt][0], boffs[pn] + b_rb0 + bc);
            ldsm_x4(bbuf[nxt][1], boffs[pn] + b_rb1 + bc);
        }
        const int p = s >> 2;
#pragma unroll
        for (int mf = 0; mf < 2; mf++)
#pragma unroll
            for (int h = 0; h < 2; h++) {
                int* d0 = (p == 0) ? accAA[mf][h * 2 + 0] : accX[mf][h * 2 + 0];
                int* d1 = (p == 0) ? accAA[mf][h * 2 + 1] : accX[mf][h * 2 + 1];
                mma_s8(d0, abuf[cur][mf], &bbuf[cur][h][0]);
                mma_s8(d1, abuf[cur][mf], &bbuf[cur][h][2]);
            }
    }
    __syncthreads();   // operand reads done before stage overwrite

    // ---- Epilogue: dequant + cosine + abs + threshold + fixup flag ----
    {
        const float* nA = (const float*)(smem + OFF_NA);
        const float* nB = (const float*)(smem + OFF_NB);
        const float* fA = (const float*)(smem + OFF_FA);
        const float* fB = (const float*)(smem + OFF_FB);
        const float* sA = (const float*)(smem + OFF_SA);
        const float* sB = (const float*)(smem + OFF_SB);
        float* stage = (float*)(smem + OFF_STAGE);

#pragma unroll
        for (int mf = 0; mf < 2; mf++) {
            int r_lo = warp_m * 32 + mf * 16 + (lane >> 2);
#pragma unroll
            for (int half = 0; half < 2; half++) {
                int r = r_lo + half * 8;
                float nr = nA[r], fr = fA[r], sr = sA[r];
#pragma unroll
                for (int ng = 0; ng < 4; ng++) {
                    int c0 = warp_n * 32 + ng * 8 + (lane & 3) * 2;
#pragma unroll
                    for (int e = 0; e < 2; e++) {
                        int c = c0 + e;
                        float D = (float)accAA[mf][ng][half * 2 + e]
                                + (float)accX[mf][ng][half * 2 + e] * 0.0078125f;
                        float t = nr * nB[c];
                        float g = (t >= COS_EPS) ? (fr * fB[c])
                                                 : (sr * sB[c] * (1.0f / COS_EPS));
                        float v = fabsf(D) * g;
                        if (fabsf(v - THRESHOLD) < FIX_WIN) {
                            unsigned idx = atomicAdd(&g_fix_cnt, 1u);
                            if (idx < MAXFIX)
                                g_fix[idx] = ((unsigned)b << 24) |
                                             ((unsigned)(i0 + r) << 12) |
                                             (unsigned)(j0 + c);
                        }
                        stage[r * STAGE_LD + c] = (v > THRESHOLD) ? v : 0.f;
                    }
                }
            }
        }
    }
    __syncthreads();

    // ---- Coalesced stores: main tile + mirror ----
    {
        const float* stage = (const float*)(smem + OFF_STAGE);
        float* outb = out + (size_t)b * NN * NN;
#pragma unroll
        for (int t = 0; t < 32; t++) {
            int idx = tid + t * 512;
            int r = idx >> 7, c = idx & 127;
            outb[(size_t)(i0 + r) * NN + (j0 + c)] = stage[r * STAGE_LD + c];
        }
        if (bx != by) {
#pragma unroll
            for (int t = 0; t < 32; t++) {
                int idx = tid + t * 512;
                int c = idx >> 7, r = idx & 127;
                outb[(size_t)(j0 + c) * NN + (i0 + r)] = stage[r * STAGE_LD + c];
            }
        }
    }
}

// ---------------------------------------------------------------------------
// Kernel D: exact fp32 fixup of near-threshold entries
// ---------------------------------------------------------------------------
__global__ void __launch_bounds__(256)
fixup_kernel(float* __restrict__ out)
{
    unsigned cnt = g_fix_cnt;
    if (cnt > MAXFIX) cnt = MAXFIX;
    for (unsigned t = blockIdx.x * blockDim.x + threadIdx.x; t < cnt;
         t += gridDim.x * blockDim.x) {
        unsigned e = g_fix[t];
        int b = e >> 24, i = (e >> 12) & 0xFFF, j = e & 0xFFF;
        const float4* hi4 = (const float4*)(g_h + ((size_t)b * NN + i) * DOUT);
        const float4* hj4 = (const float4*)(g_h + ((size_t)b * NN + j) * DOUT);
        float dot = 0.f;
#pragma unroll
        for (int k = 0; k < 32; k++) {
            float4 a = hi4[k], c = hj4[k];
            dot += a.x * c.x + a.y * c.y + a.z * c.z + a.w * c.w;
        }
        float denom = fmaxf(g_norm[(size_t)b * NN + i] * g_norm[(size_t)b * NN + j],
                            COS_EPS);
        float v = fabsf(dot) / denom;
        float r = (v > THRESHOLD) ? v : 0.f;
        float* outb = out + (size_t)b * NN * NN;
        outb[(size_t)i * NN + j] = r;
        outb[(size_t)j * NN + i] = r;
    }
}

// ---------------------------------------------------------------------------
extern "C" void kernel_launch(void* const* d_in, const int* in_sizes, int n_in,
                              void* d_out, int out_size)
{
    (void)in_sizes; (void)n_in; (void)out_size;
    const float* z = (const float*)d_in[0];
    const float* W = (const float*)d_in[1];
    float* out = (float*)d_out;

    const int smem1 = (64 * Z_ROWLEN + 64 * DOUT) * sizeof(float);

    static bool attrs_set = false;
    if (!attrs_set) {
        cudaFuncSetAttribute(gemm1_kernel, cudaFuncAttributeMaxDynamicSharedMemorySize, smem1);
        cudaFuncSetAttribute(gram_imma_kernel, cudaFuncAttributeMaxDynamicSharedMemorySize, GRAM_SMEM);
        attrs_set = true;
    }

    reset_kernel<<<1, 1>>>();
    gemm1_kernel<<<BB * NN / 128, 256, smem1>>>(z, W);
    dim3 grid(528, BB);
    gram_imma_kernel<<<grid, 512, GRAM_SMEM>>>(out);
    fixup_kernel<<<128, 256>>>(out);
}

// round 8
// speedup vs baseline: 1.8713x; 1.8713x over previous
#include <cuda_runtime.h>
#include <cuda_fp16.h>
#include <cstdint>
#include <cstddef>

// Problem constants
#define BB    4
#define NN    4096
#define DIN   256
#define DOUT  128
#define COS_EPS    0.001f
#define THRESHOLD  0.1f
#define LEAKY      0.01f
#define FIX_WIN    2e-4f
#define MAXFIX     (1u << 22)

// ---------------------------------------------------------------------------
// Scratch (static device globals; no allocations allowed)
// ---------------------------------------------------------------------------
__device__ float          g_h[BB * NN * DOUT];     // fp32 h (fixup)
__device__ __half         g_hf[BB * NN * DOUT];    // fp16 h (gram operand)
__device__ float          g_norm[BB * NN];
__device__ float          g_rnorm[BB * NN];
__device__ unsigned int   g_fix_cnt;
__device__ unsigned int   g_fix[MAXFIX];

__device__ __forceinline__ uint32_t smem_u32(const void* p) {
    uint32_t a;
    asm("{ .reg .u64 t; cvta.to.shared.u64 t, %1; cvt.u32.u64 %0, t; }"
        : "=r"(a) : "l"(p));
    return a;
}

__device__ __forceinline__ void ldsm_x4(uint32_t* r, uint32_t addr) {
    asm volatile("ldmatrix.sync.aligned.m8n8.x4.shared.b16 {%0,%1,%2,%3}, [%4];"
                 : "=r"(r[0]), "=r"(r[1]), "=r"(r[2]), "=r"(r[3]) : "r"(addr));
}
__device__ __forceinline__ void mma_f16(float* d, const uint32_t* a, const uint32_t* b) {
    asm volatile(
        "mma.sync.aligned.m16n8k16.row.col.f32.f16.f16.f32 "
        "{%0,%1,%2,%3}, {%4,%5,%6,%7}, {%8,%9}, {%0,%1,%2,%3};"
        : "+f"(d[0]), "+f"(d[1]), "+f"(d[2]), "+f"(d[3])
        : "r"(a[0]), "r"(a[1]), "r"(a[2]), "r"(a[3]), "r"(b[0]), "r"(b[1]));
}

extern __shared__ char smem_raw[];

// ---------------------------------------------------------------------------
// Kernel A: h = leaky_relu(z @ W) + fused row norms + fp16 cast
// ---------------------------------------------------------------------------
#define Z_ROWLEN 132
__global__ void __launch_bounds__(256, 1)
gemm1_kernel(const float* __restrict__ z, const float* __restrict__ W)
{
    float* smem = (float*)smem_raw;
    float* Zs = smem;
    float* Ws = smem + 64 * Z_ROWLEN;

    const int m0  = blockIdx.x * 128;
    const int tid = threadIdx.x;
    const int tm  = tid >> 4;
    const int tn  = tid & 15;

    float acc[8][8];
#pragma unroll
    for (int i = 0; i < 8; i++)
#pragma unroll
        for (int j = 0; j < 8; j++) acc[i][j] = 0.f;

    for (int k0 = 0; k0 < DIN; k0 += 64) {
#pragma unroll
        for (int t = 0; t < 8; t++) {
            int idx = tid + t * 256;
            int r   = idx >> 4;
            int kk  = (idx & 15) << 2;
            float4 v = *(const float4*)(z + (size_t)(m0 + r) * DIN + k0 + kk);
            Zs[(kk + 0) * Z_ROWLEN + r] = v.x;
            Zs[(kk + 1) * Z_ROWLEN + r] = v.y;
            Zs[(kk + 2) * Z_ROWLEN + r] = v.z;
            Zs[(kk + 3) * Z_ROWLEN + r] = v.w;
        }
#pragma unroll
        for (int t = 0; t < 8; t++) {
            int idx = tid + t * 256;
            int kk  = idx >> 5;
            int n4  = (idx & 31) << 2;
            float4 v = *(const float4*)(W + (size_t)(k0 + kk) * DOUT + n4);
            *(float4*)&Ws[kk * DOUT + n4] = v;
        }
        __syncthreads();

#pragma unroll 8
        for (int k = 0; k < 64; k++) {
            float a[8], b[8];
            *(float4*)(a)     = *(float4*)&Zs[k * Z_ROWLEN + tm * 8];
            *(float4*)(a + 4) = *(float4*)&Zs[k * Z_ROWLEN + tm * 8 + 4];
            *(float4*)(b)     = *(float4*)&Ws[k * DOUT + tn * 8];
            *(float4*)(b + 4) = *(float4*)&Ws[k * DOUT + tn * 8 + 4];
#pragma unroll
            for (int i = 0; i < 8; i++)
#pragma unroll
                for (int j = 0; j < 8; j++)
                    acc[i][j] += a[i] * b[j];
        }
        __syncthreads();
    }

    // Epilogue: leaky relu, row norm (16-lane reduction), fp32 + fp16 stores
#pragma unroll
    for (int i = 0; i < 8; i++) {
        int row = m0 + tm * 8 + i;
        float vv[8];
        float ss = 0.f;
#pragma unroll
        for (int j = 0; j < 8; j++) {
            float x = acc[i][j];
            float v = (x > 0.f) ? x : LEAKY * x;
            vv[j] = v;
            ss += v * v;
        }
#pragma unroll
        for (int off = 1; off < 16; off <<= 1)
            ss += __shfl_xor_sync(0xFFFFFFFFu, ss, off);

        float* dst = g_h + (size_t)row * DOUT + tn * 8;
        *(float4*)(dst)     = make_float4(vv[0], vv[1], vv[2], vv[3]);
        *(float4*)(dst + 4) = make_float4(vv[4], vv[5], vv[6], vv[7]);

        union { __half2 h2[4]; uint4 u; } ph;
        ph.h2[0] = __floats2half2_rn(vv[0], vv[1]);
        ph.h2[1] = __floats2half2_rn(vv[2], vv[3]);
        ph.h2[2] = __floats2half2_rn(vv[4], vv[5]);
        ph.h2[3] = __floats2half2_rn(vv[6], vv[7]);
        *(uint4*)(g_hf + (size_t)row * DOUT + tn * 8) = ph.u;

        if (tn == 0) {
            float n = sqrtf(ss);
            g_norm[row]  = n;
            g_rnorm[row] = (n > 0.f) ? (1.0f / n) : 0.f;
        }
    }
}

__global__ void reset_kernel() { g_fix_cnt = 0; }

// ---------------------------------------------------------------------------
// Kernel C: fp16 single-pass Gram (near-threshold entries recomputed exactly
// by fixup_kernel). 512 threads, 16 warps (4m x 4n), warp tile 32x32,
// K=128 smem-resident (8 ksteps), double-buffered fragments.
// Triangular grid: blockIdx.x in [0,528) -> (bx,by), by >= bx.
// ---------------------------------------------------------------------------
#define OFF_A       0
#define OFF_B       32768
#define OFF_PARAMS  66048                 /* after stage (128*129*4) */
#define OFF_NA      (OFF_PARAMS)
#define OFF_NB      (OFF_PARAMS + 512)
#define OFF_RNA     (OFF_PARAMS + 1024)
#define OFF_RNB     (OFF_PARAMS + 1536)
#define GRAM_SMEM   (OFF_PARAMS + 2048)
#define OFF_STAGE   0
#define STAGE_LD    129

__global__ void __launch_bounds__(512, 1)
gram_f16_kernel(float* __restrict__ out)
{
    // Triangular tile index -> (bx, by) with by >= bx
    int tt = blockIdx.x;
    int by = (int)((sqrtf(8.f * tt + 1.f) - 1.f) * 0.5f);
    while ((by + 1) * (by + 2) / 2 <= tt) by++;
    while (by * (by + 1) / 2 > tt) by--;
    const int bx = tt - by * (by + 1) / 2;
    const int b  = blockIdx.y;

    char* smem = smem_raw;
    const uint32_t sb = smem_u32(smem);
    const int tid  = threadIdx.x;
    const int lane = tid & 31;
    const int wid  = tid >> 5;
    const int warp_m = wid >> 2;
    const int warp_n = wid & 3;

    const int i0 = bx * 128, j0 = by * 128;
    const size_t hbase = (size_t)b * NN * DOUT;
    const size_t nbase = (size_t)b * NN;

    // ---- Load fp16 operand tiles (32KB each), XOR-swizzled 256B rows ----
    {
        const uint4* srcA = (const uint4*)(g_hf + hbase + (size_t)i0 * DOUT);
        const uint4* srcB = (const uint4*)(g_hf + hbase + (size_t)j0 * DOUT);
#pragma unroll
        for (int t = 0; t < 4; t++) {
            int idx = tid + t * 512;            // 0..2047 16B chunks
            int row = idx >> 4;                 // 16 chunks per 256B row
            int c   = idx & 15;
            uint32_t off = (uint32_t)(row * 256) + (uint32_t)((c ^ (row & 7)) << 4);
            *(uint4*)(smem + OFF_A + off) = srcA[idx];
            *(uint4*)(smem + OFF_B + off) = srcB[idx];
        }
        if (tid < 128) {
            ((float*)(smem + OFF_NA))[tid]  = g_norm[nbase + i0 + tid];
            ((float*)(smem + OFF_NB))[tid]  = g_norm[nbase + j0 + tid];
            ((float*)(smem + OFF_RNA))[tid] = g_rnorm[nbase + i0 + tid];
            ((float*)(smem + OFF_RNB))[tid] = g_rnorm[nbase + j0 + tid];
        }
    }
    __syncthreads();

    // ---- MMA mainloop: single pass, 8 ksteps of 16, pipelined ----
    float acc[2][4][4];
#pragma unroll
    for (int mf = 0; mf < 2; mf++)
#pragma unroll
        for (int nf = 0; nf < 4; nf++)
#pragma unroll
            for (int r = 0; r < 4; r++) acc[mf][nf][r] = 0.f;

    const uint32_t abase = sb + OFF_A;
    const uint32_t bbase = sb + OFF_B;

    // A fragment: rows warp_m*32 + mf*16 + (lane&15), k-half = lane>>4
    const int a_row  = warp_m * 32 + (lane & 15);
    const int a_ksel = lane >> 4;
    const int a_swz  = a_row & 7;
    const uint32_t a_rb0 = (uint32_t)(a_row * 256);
    const uint32_t a_rb1 = (uint32_t)((a_row + 16) * 256);
    // B fragment (non-trans): n-rows warp_n*32 + q*16 + (lane&7)+((lane>>4)<<3)
    const int b_row  = warp_n * 32 + (lane & 7) + ((lane >> 4) << 3);
    const int b_ksel = (lane >> 3) & 1;
    const int b_swz  = b_row & 7;
    const uint32_t b_rb0 = (uint32_t)(b_row * 256);
    const uint32_t b_rb1 = (uint32_t)((b_row + 16) * 256);

    uint32_t abuf[2][2][4], bbuf[2][2][4];

    // prefetch kstep 0
    {
        uint32_t ac = (uint32_t)((a_ksel) ^ a_swz) << 4;
        uint32_t bc = (uint32_t)((b_ksel) ^ b_swz) << 4;
        ldsm_x4(abuf[0][0], abase + a_rb0 + ac);
        ldsm_x4(abuf[0][1], abase + a_rb1 + ac);
        ldsm_x4(bbuf[0][0], bbase + b_rb0 + bc);
        ldsm_x4(bbuf[0][1], bbase + b_rb1 + bc);
    }

#pragma unroll
    for (int s = 0; s < 8; s++) {
        const int cur = s & 1;
        if (s < 7) {
            const int kn = s + 1;
            const int nxt = kn & 1;
            uint32_t ac = (uint32_t)((kn * 2 + a_ksel) ^ a_swz) << 4;
            uint32_t bc = (uint32_t)((kn * 2 + b_ksel) ^ b_swz) << 4;
            ldsm_x4(abuf[nxt][0], abase + a_rb0 + ac);
            ldsm_x4(abuf[nxt][1], abase + a_rb1 + ac);
            ldsm_x4(bbuf[nxt][0], bbase + b_rb0 + bc);
            ldsm_x4(bbuf[nxt][1], bbase + b_rb1 + bc);
        }
#pragma unroll
        for (int mf = 0; mf < 2; mf++)
#pragma unroll
            for (int q = 0; q < 2; q++) {
                mma_f16(acc[mf][q * 2 + 0], abuf[cur][mf], &bbuf[cur][q][0]);
                mma_f16(acc[mf][q * 2 + 1], abuf[cur][mf], &bbuf[cur][q][2]);
            }
    }
    __syncthreads();   // operand reads done before stage overwrite

    // ---- Epilogue: cosine + abs + threshold + fixup flag, into staging ----
    {
        const float* nA  = (const float*)(smem + OFF_NA);
        const float* nB  = (const float*)(smem + OFF_NB);
        const float* rnA = (const float*)(smem + OFF_RNA);
        const float* rnB = (const float*)(smem + OFF_RNB);
        float* stage = (float*)(smem + OFF_STAGE);

#pragma unroll
        for (int mf = 0; mf < 2; mf++) {
            int r_lo = warp_m * 32 + mf * 16 + (lane >> 2);
#pragma unroll
            for (int half = 0; half < 2; half++) {
                int r = r_lo + half * 8;
                float nm = nA[r], rnm = rnA[r];
#pragma unroll
                for (int nf = 0; nf < 4; nf++) {
                    int c0 = warp_n * 32 + nf * 8 + (lane & 3) * 2;
#pragma unroll
                    for (int e = 0; e < 2; e++) {
                        int c = c0 + e;
                        float dot = acc[mf][nf][half * 2 + e];
                        float t = nm * nB[c];
                        float f = (t >= COS_EPS) ? (rnm * rnB[c]) : (1.0f / COS_EPS);
                        float v = fabsf(dot) * f;
                        if (fabsf(v - THRESHOLD) < FIX_WIN) {
                            unsigned idx = atomicAdd(&g_fix_cnt, 1u);
                            if (idx < MAXFIX)
                                g_fix[idx] = ((unsigned)b << 24) |
                                             ((unsigned)(i0 + r) << 12) |
                                             (unsigned)(j0 + c);
                        }
                        stage[r * STAGE_LD + c] = (v > THRESHOLD) ? v : 0.f;
                    }
                }
            }
        }
    }
    __syncthreads();

    // ---- Coalesced stores: main tile + mirror ----
    {
        const float* stage = (const float*)(smem + OFF_STAGE);
        float* outb = out + (size_t)b * NN * NN;
#pragma unroll
        for (int t = 0; t < 32; t++) {
            int idx = tid + t * 512;
            int r = idx >> 7, c = idx & 127;
            outb[(size_t)(i0 + r) * NN + (j0 + c)] = stage[r * STAGE_LD + c];
        }
        if (bx != by) {
#pragma unroll
            for (int t = 0; t < 32; t++) {
                int idx = tid + t * 512;
                int c = idx >> 7, r = idx & 127;
                outb[(size_t)(j0 + c) * NN + (i0 + r)] = stage[r * STAGE_LD + c];
            }
        }
    }
}

// ---------------------------------------------------------------------------
// Kernel D: exact fp32 fixup of near-threshold entries
// ---------------------------------------------------------------------------
__global__ void __launch_bounds__(256)
fixup_kernel(float* __restrict__ out)
{
    unsigned cnt = g_fix_cnt;
    if (cnt > MAXFIX) cnt = MAXFIX;
    for (unsigned t = blockIdx.x * blockDim.x + threadIdx.x; t < cnt;
         t += gridDim.x * blockDim.x) {
        unsigned e = g_fix[t];
        int b = e >> 24, i = (e >> 12) & 0xFFF, j = e & 0xFFF;
        const float4* hi4 = (const float4*)(g_h + ((size_t)b * NN + i) * DOUT);
        const float4* hj4 = (const float4*)(g_h + ((size_t)b * NN + j) * DOUT);
        float dot = 0.f;
#pragma unroll
        for (int k = 0; k < 32; k++) {
            float4 a = hi4[k], c = hj4[k];
            dot += a.x * c.x + a.y * c.y + a.z * c.z + a.w * c.w;
        }
        float denom = fmaxf(g_norm[(size_t)b * NN + i] * g_norm[(size_t)b * NN + j],
                            COS_EPS);
        float v = fabsf(dot) / denom;
        float r = (v > THRESHOLD) ? v : 0.f;
        float* outb = out + (size_t)b * NN * NN;
        outb[(size_t)i * NN + j] = r;
        outb[(size_t)j * NN + i] = r;
    }
}

// ---------------------------------------------------------------------------
extern "C" void kernel_launch(void* const* d_in, const int* in_sizes, int n_in,
                              void* d_out, int out_size)
{
    (void)in_sizes; (void)n_in; (void)out_size;
    const float* z = (const float*)d_in[0];
    const float* W = (const float*)d_in[1];
    float* out = (float*)d_out;

    const int smem1 = (64 * Z_ROWLEN + 64 * DOUT) * sizeof(float);

    static bool attrs_set = false;
    if (!attrs_set) {
        cudaFuncSetAttribute(gemm1_kernel, cudaFuncAttributeMaxDynamicSharedMemorySize, smem1);
        cudaFuncSetAttribute(gram_f16_kernel, cudaFuncAttributeMaxDynamicSharedMemorySize, GRAM_SMEM);
        attrs_set = true;
    }

    reset_kernel<<<1, 1>>>();
    gemm1_kernel<<<BB * NN / 128, 256, smem1>>>(z, W);
    dim3 grid(528, BB);
    gram_f16_kernel<<<grid, 512, GRAM_SMEM>>>(out);
    fixup_kernel<<<128, 256>>>(out);
}

// round 9
// speedup vs baseline: 2.3001x; 1.2291x over previous
#include <cuda_runtime.h>
#include <cuda_fp16.h>
#include <cstdint>
#include <cstddef>

// Problem constants
#define BB    4
#define NN    4096
#define DIN   256
#define DOUT  128
#define COS_EPS    0.001f
#define THRESHOLD  0.1f
#define LEAKY      0.01f
#define FIX_WIN    2e-4f
#define MAXFIX     (1u << 22)

// ---------------------------------------------------------------------------
// Scratch (static device globals; no allocations allowed)
// ---------------------------------------------------------------------------
__device__ float          g_h[BB * NN * DOUT];     // fp32 h (fixup)
__device__ __half         g_hf[BB * NN * DOUT];    // fp16 h (gram operand)
__device__ float          g_norm[BB * NN];
__device__ float          g_rnorm[BB * NN];
__device__ unsigned int   g_fix_cnt;
__device__ unsigned int   g_fix[MAXFIX];

__device__ __forceinline__ uint32_t smem_u32(const void* p) {
    uint32_t a;
    asm("{ .reg .u64 t; cvta.to.shared.u64 t, %1; cvt.u32.u64 %0, t; }"
        : "=r"(a) : "l"(p));
    return a;
}

__device__ __forceinline__ void ldsm_x4(uint32_t* r, uint32_t addr) {
    asm volatile("ldmatrix.sync.aligned.m8n8.x4.shared.b16 {%0,%1,%2,%3}, [%4];"
                 : "=r"(r[0]), "=r"(r[1]), "=r"(r[2]), "=r"(r[3]) : "r"(addr));
}
__device__ __forceinline__ void mma_f16(float* d, const uint32_t* a, const uint32_t* b) {
    asm volatile(
        "mma.sync.aligned.m16n8k16.row.col.f32.f16.f16.f32 "
        "{%0,%1,%2,%3}, {%4,%5,%6,%7}, {%8,%9}, {%0,%1,%2,%3};"
        : "+f"(d[0]), "+f"(d[1]), "+f"(d[2]), "+f"(d[3])
        : "r"(a[0]), "r"(a[1]), "r"(a[2]), "r"(a[3]), "r"(b[0]), "r"(b[1]));
}

extern __shared__ char smem_raw[];

// ---------------------------------------------------------------------------
// Kernel A: h = leaky_relu(z @ W) + fused row norms + fp16 cast
// ---------------------------------------------------------------------------
#define Z_ROWLEN 132
__global__ void __launch_bounds__(256, 1)
gemm1_kernel(const float* __restrict__ z, const float* __restrict__ W)
{
    float* smem = (float*)smem_raw;
    float* Zs = smem;
    float* Ws = smem + 64 * Z_ROWLEN;

    const int m0  = blockIdx.x * 128;
    const int tid = threadIdx.x;
    const int tm  = tid >> 4;
    const int tn  = tid & 15;

    float acc[8][8];
#pragma unroll
    for (int i = 0; i < 8; i++)
#pragma unroll
        for (int j = 0; j < 8; j++) acc[i][j] = 0.f;

    for (int k0 = 0; k0 < DIN; k0 += 64) {
#pragma unroll
        for (int t = 0; t < 8; t++) {
            int idx = tid + t * 256;
            int r   = idx >> 4;
            int kk  = (idx & 15) << 2;
            float4 v = *(const float4*)(z + (size_t)(m0 + r) * DIN + k0 + kk);
            Zs[(kk + 0) * Z_ROWLEN + r] = v.x;
            Zs[(kk + 1) * Z_ROWLEN + r] = v.y;
            Zs[(kk + 2) * Z_ROWLEN + r] = v.z;
            Zs[(kk + 3) * Z_ROWLEN + r] = v.w;
        }
#pragma unroll
        for (int t = 0; t < 8; t++) {
            int idx = tid + t * 256;
            int kk  = idx >> 5;
            int n4  = (idx & 31) << 2;
            float4 v = *(const float4*)(W + (size_t)(k0 + kk) * DOUT + n4);
            *(float4*)&Ws[kk * DOUT + n4] = v;
        }
        __syncthreads();

#pragma unroll 8
        for (int k = 0; k < 64; k++) {
            float a[8], b[8];
            *(float4*)(a)     = *(float4*)&Zs[k * Z_ROWLEN + tm * 8];
            *(float4*)(a + 4) = *(float4*)&Zs[k * Z_ROWLEN + tm * 8 + 4];
            *(float4*)(b)     = *(float4*)&Ws[k * DOUT + tn * 8];
            *(float4*)(b + 4) = *(float4*)&Ws[k * DOUT + tn * 8 + 4];
#pragma unroll
            for (int i = 0; i < 8; i++)
#pragma unroll
                for (int j = 0; j < 8; j++)
                    acc[i][j] += a[i] * b[j];
        }
        __syncthreads();
    }

    // Epilogue: leaky relu, row norm (16-lane reduction), fp32 + fp16 stores
#pragma unroll
    for (int i = 0; i < 8; i++) {
        int row = m0 + tm * 8 + i;
        float vv[8];
        float ss = 0.f;
#pragma unroll
        for (int j = 0; j < 8; j++) {
            float x = acc[i][j];
            float v = (x > 0.f) ? x : LEAKY * x;
            vv[j] = v;
            ss += v * v;
        }
#pragma unroll
        for (int off = 1; off < 16; off <<= 1)
            ss += __shfl_xor_sync(0xFFFFFFFFu, ss, off);

        float* dst = g_h + (size_t)row * DOUT + tn * 8;
        *(float4*)(dst)     = make_float4(vv[0], vv[1], vv[2], vv[3]);
        *(float4*)(dst + 4) = make_float4(vv[4], vv[5], vv[6], vv[7]);

        union { __half2 h2[4]; uint4 u; } ph;
        ph.h2[0] = __floats2half2_rn(vv[0], vv[1]);
        ph.h2[1] = __floats2half2_rn(vv[2], vv[3]);
        ph.h2[2] = __floats2half2_rn(vv[4], vv[5]);
        ph.h2[3] = __floats2half2_rn(vv[6], vv[7]);
        *(uint4*)(g_hf + (size_t)row * DOUT + tn * 8) = ph.u;

        if (tn == 0) {
            float n = sqrtf(ss);
            g_norm[row]  = n;
            g_rnorm[row] = (n > 0.f) ? (1.0f / n) : 0.f;
        }
    }
}

__global__ void reset_kernel() { g_fix_cnt = 0; }

// ---------------------------------------------------------------------------
// Kernel C: fp16 single-pass Gram, 512 threads, 16 warps (4m x 4n),
// warp tile 32x32, K=128 smem-resident, single-buffered fragments
// (HMMA-throughput bound — pipelining proven irrelevant R5/R6),
// __launch_bounds__(512, 2): 2 CTAs/SM so load/epilogue/store phases of one
// CTA overlap the other's MMA stream.
// Triangular grid: blockIdx.x in [0,528) -> (bx,by), by >= bx.
// ---------------------------------------------------------------------------
#define OFF_A       0
#define OFF_B       32768
#define OFF_PARAMS  66048                 /* after stage (128*129*4) */
#define OFF_NA      (OFF_PARAMS)
#define OFF_NB      (OFF_PARAMS + 512)
#define OFF_RNA     (OFF_PARAMS + 1024)
#define OFF_RNB     (OFF_PARAMS + 1536)
#define GRAM_SMEM   (OFF_PARAMS + 2048)
#define OFF_STAGE   0
#define STAGE_LD    129

__global__ void __launch_bounds__(512, 2)
gram_f16_kernel(float* __restrict__ out)
{
    // Triangular tile index -> (bx, by) with by >= bx
    int tt = blockIdx.x;
    int by = (int)((sqrtf(8.f * tt + 1.f) - 1.f) * 0.5f);
    while ((by + 1) * (by + 2) / 2 <= tt) by++;
    while (by * (by + 1) / 2 > tt) by--;
    const int bx = tt - by * (by + 1) / 2;
    const int b  = blockIdx.y;

    char* smem = smem_raw;
    const uint32_t sb = smem_u32(smem);
    const int tid  = threadIdx.x;
    const int lane = tid & 31;
    const int wid  = tid >> 5;
    const int warp_m = wid >> 2;
    const int warp_n = wid & 3;

    const int i0 = bx * 128, j0 = by * 128;
    const size_t hbase = (size_t)b * NN * DOUT;
    const size_t nbase = (size_t)b * NN;

    // ---- Load fp16 operand tiles (32KB each), XOR-swizzled 256B rows ----
    {
        const uint4* srcA = (const uint4*)(g_hf + hbase + (size_t)i0 * DOUT);
        const uint4* srcB = (const uint4*)(g_hf + hbase + (size_t)j0 * DOUT);
#pragma unroll
        for (int t = 0; t < 4; t++) {
            int idx = tid + t * 512;            // 0..2047 16B chunks
            int row = idx >> 4;                 // 16 chunks per 256B row
            int c   = idx & 15;
            uint32_t off = (uint32_t)(row * 256) + (uint32_t)((c ^ (row & 7)) << 4);
            *(uint4*)(smem + OFF_A + off) = srcA[idx];
            *(uint4*)(smem + OFF_B + off) = srcB[idx];
        }
        if (tid < 128) {
            ((float*)(smem + OFF_NA))[tid]  = g_norm[nbase + i0 + tid];
            ((float*)(smem + OFF_NB))[tid]  = g_norm[nbase + j0 + tid];
            ((float*)(smem + OFF_RNA))[tid] = g_rnorm[nbase + i0 + tid];
            ((float*)(smem + OFF_RNB))[tid] = g_rnorm[nbase + j0 + tid];
        }
    }
    __syncthreads();

    // ---- MMA mainloop: single pass, 8 ksteps of 16, single-buffered ----
    float acc[2][4][4];
#pragma unroll
    for (int mf = 0; mf < 2; mf++)
#pragma unroll
        for (int nf = 0; nf < 4; nf++)
#pragma unroll
            for (int r = 0; r < 4; r++) acc[mf][nf][r] = 0.f;

    const uint32_t abase = sb + OFF_A;
    const uint32_t bbase = sb + OFF_B;

    // A fragment: rows warp_m*32 + mf*16 + (lane&15), k-half = lane>>4
    const int a_row  = warp_m * 32 + (lane & 15);
    const int a_ksel = lane >> 4;
    const int a_swz  = a_row & 7;
    const uint32_t a_rb0 = (uint32_t)(a_row * 256);
    const uint32_t a_rb1 = (uint32_t)((a_row + 16) * 256);
    // B fragment (non-trans): n-rows warp_n*32 + q*16 + (lane&7)+((lane>>4)<<3)
    const int b_row  = warp_n * 32 + (lane & 7) + ((lane >> 4) << 3);
    const int b_ksel = (lane >> 3) & 1;
    const int b_swz  = b_row & 7;
    const uint32_t b_rb0 = (uint32_t)(b_row * 256);
    const uint32_t b_rb1 = (uint32_t)((b_row + 16) * 256);

#pragma unroll
    for (int s = 0; s < 8; s++) {
        uint32_t abuf[2][4], bbuf[2][4];
        uint32_t ac = (uint32_t)((s * 2 + a_ksel) ^ a_swz) << 4;
        uint32_t bc = (uint32_t)((s * 2 + b_ksel) ^ b_swz) << 4;
        ldsm_x4(abuf[0], abase + a_rb0 + ac);
        ldsm_x4(abuf[1], abase + a_rb1 + ac);
        ldsm_x4(bbuf[0], bbase + b_rb0 + bc);
        ldsm_x4(bbuf[1], bbase + b_rb1 + bc);
#pragma unroll
        for (int mf = 0; mf < 2; mf++)
#pragma unroll
            for (int q = 0; q < 2; q++) {
                mma_f16(acc[mf][q * 2 + 0], abuf[mf], &bbuf[q][0]);
                mma_f16(acc[mf][q * 2 + 1], abuf[mf], &bbuf[q][2]);
            }
    }
    __syncthreads();   // operand reads done before stage overwrite

    // ---- Epilogue: cosine + abs + threshold + fixup flag, into staging ----
    {
        const float* nA  = (const float*)(smem + OFF_NA);
        const float* nB  = (const float*)(smem + OFF_NB);
        const float* rnA = (const float*)(smem + OFF_RNA);
        const float* rnB = (const float*)(smem + OFF_RNB);
        float* stage = (float*)(smem + OFF_STAGE);

#pragma unroll
        for (int mf = 0; mf < 2; mf++) {
            int r_lo = warp_m * 32 + mf * 16 + (lane >> 2);
#pragma unroll
            for (int half = 0; half < 2; half++) {
                int r = r_lo + half * 8;
                float nm = nA[r], rnm = rnA[r];
#pragma unroll
                for (int nf = 0; nf < 4; nf++) {
                    int c0 = warp_n * 32 + nf * 8 + (lane & 3) * 2;
#pragma unroll
                    for (int e = 0; e < 2; e++) {
                        int c = c0 + e;
                        float dot = acc[mf][nf][half * 2 + e];
                        float t = nm * nB[c];
                        float f = (t >= COS_EPS) ? (rnm * rnB[c]) : (1.0f / COS_EPS);
                        float v = fabsf(dot) * f;
                        if (fabsf(v - THRESHOLD) < FIX_WIN) {
                            unsigned idx = atomicAdd(&g_fix_cnt, 1u);
                            if (idx < MAXFIX)
                                g_fix[idx] = ((unsigned)b << 24) |
                                             ((unsigned)(i0 + r) << 12) |
                                             (unsigned)(j0 + c);
                        }
                        stage[r * STAGE_LD + c] = (v > THRESHOLD) ? v : 0.f;
                    }
                }
            }
        }
    }
    __syncthreads();

    // ---- Coalesced stores: main tile + mirror ----
    {
        const float* stage = (const float*)(smem + OFF_STAGE);
        float* outb = out + (size_t)b * NN * NN;
#pragma unroll
        for (int t = 0; t < 32; t++) {
            int idx = tid + t * 512;
            int r = idx >> 7, c = idx & 127;
            outb[(size_t)(i0 + r) * NN + (j0 + c)] = stage[r * STAGE_LD + c];
        }
        if (bx != by) {
#pragma unroll
            for (int t = 0; t < 32; t++) {
                int idx = tid + t * 512;
                int c = idx >> 7, r = idx & 127;
                outb[(size_t)(j0 + c) * NN + (i0 + r)] = stage[r * STAGE_LD + c];
            }
        }
    }
}

// ---------------------------------------------------------------------------
// Kernel D: exact fp32 fixup of near-threshold entries
// ---------------------------------------------------------------------------
__global__ void __launch_bounds__(256)
fixup_kernel(float* __restrict__ out)
{
    unsigned cnt = g_fix_cnt;
    if (cnt > MAXFIX) cnt = MAXFIX;
    for (unsigned t = blockIdx.x * blockDim.x + threadIdx.x; t < cnt;
         t += gridDim.x * blockDim.x) {
        unsigned e = g_fix[t];
        int b = e >> 24, i = (e >> 12) & 0xFFF, j = e & 0xFFF;
        const float4* hi4 = (const float4*)(g_h + ((size_t)b * NN + i) * DOUT);
        const float4* hj4 = (const float4*)(g_h + ((size_t)b * NN + j) * DOUT);
        float dot = 0.f;
#pragma unroll
        for (int k = 0; k < 32; k++) {
            float4 a = hi4[k], c = hj4[k];
            dot += a.x * c.x + a.y * c.y + a.z * c.z + a.w * c.w;
        }
        float denom = fmaxf(g_norm[(size_t)b * NN + i] * g_norm[(size_t)b * NN + j],
                            COS_EPS);
        float v = fabsf(dot) / denom;
        float r = (v > THRESHOLD) ? v : 0.f;
        float* outb = out + (size_t)b * NN * NN;
        outb[(size_t)i * NN + j] = r;
        outb[(size_t)j * NN + i] = r;
    }
}

// ---------------------------------------------------------------------------
extern "C" void kernel_launch(void* const* d_in, const int* in_sizes, int n_in,
                              void* d_out, int out_size)
{
    (void)in_sizes; (void)n_in; (void)out_size;
    const float* z = (const float*)d_in[0];
    const float* W = (const float*)d_in[1];
    float* out = (float*)d_out;

    const int smem1 = (64 * Z_ROWLEN + 64 * DOUT) * sizeof(float);

    static bool attrs_set = false;
    if (!attrs_set) {
        cudaFuncSetAttribute(gemm1_kernel, cudaFuncAttributeMaxDynamicSharedMemorySize, smem1);
        cudaFuncSetAttribute(gram_f16_kernel, cudaFuncAttributeMaxDynamicSharedMemorySize, GRAM_SMEM);
        attrs_set = true;
    }

    reset_kernel<<<1, 1>>>();
    gemm1_kernel<<<BB * NN / 128, 256, smem1>>>(z, W);
    dim3 grid(528, BB);
    gram_f16_kernel<<<grid, 512, GRAM_SMEM>>>(out);
    fixup_kernel<<<1024, 256>>>(out);
}